// round 14
// baseline (speedup 1.0000x reference)
#include <cuda_runtime.h>
#include <math.h>

#define N_MAX   65536
#define NF      64
#define LORD    5
#define RING    2048
#define NWARP   16
#define M32N    (N_MAX / 32)
#define ZCLAMP  801          // COEFF_VEC_SIZE(807) - (L_ORDER+1)
#define IB_SAMP 1024         // samples per interp block
#define IB_THR  256
#define W_INF   0.26794919243112270647f   // 2 - sqrt(3)

// ---------------- device scratch (no allocations allowed) ----------------
__device__ __align__(16) float4 g_vals4[N_MAX * 2];  // per sample: v0..v5, x, z_bits
__device__ int g_zmm[M32N];                          // per 32-sample: zmin | zmax<<16

__device__ __forceinline__ float tin_f(int i) {
    return (float)((double)i / 63.0);
}

__device__ __forceinline__ int ld_acq(const int* p) {
    int v;
    asm volatile("ld.acquire.cta.u32 %0, [%1];" : "=r"(v) : "l"(p) : "memory");
    return v;
}
__device__ __forceinline__ void st_rel(int* p, int v) {
    asm volatile("st.release.cta.u32 [%0], %1;" :: "l"(p), "r"(v) : "memory");
}

// ---------------- kernel 1: fused prep (per-block) + spline eval + taps ----------------
__global__ void __launch_bounds__(IB_THR)
interp_kernel(const float* __restrict__ delay, const float* __restrict__ raw,
              const float* __restrict__ exc, int burst, int n) {
    __shared__ float yf[6][NF];
    __shared__ float w[62];
    __shared__ float dpS[6][62];
    __shared__ float Ms[6][64];
    __shared__ float spy[6][64];
    __shared__ float spb[6][63];
    __shared__ float spc[6][63];
    __shared__ float spd[6][63];
    int tid = threadIdx.x;
    if (burst > n) burst = n;

    if (tid < NF) {
        float s[LORD]; float sum = 0.f;
        #pragma unroll
        for (int l = 0; l < LORD; l++) {
            s[l] = 1.0f / (1.0f + expf(-raw[tid * LORD + l]));
            sum += s[l];
        }
        #pragma unroll
        for (int l = 0; l < LORD; l++) yf[1 + l][tid] = s[l] / sum;
        yf[0][tid] = delay[tid];
    }
    if (tid == IB_THR - 1) {
        float wv = 0.25f; w[0] = wv;
        #pragma unroll
        for (int k = 1; k < 20; k++) { wv = 1.0f / (4.0f - wv); w[k] = wv; }
        #pragma unroll
        for (int k = 20; k < 62; k++) w[k] = W_INF;
    }
    __syncthreads();

    if (tid < 6) {
        const float rs = 6.0f * 63.0f * 63.0f;
        float yim1 = yf[tid][0];
        float yi   = yf[tid][1];
        float prev = 0.f;
        #pragma unroll
        for (int k = 0; k < 62; k++) {
            float yip1 = yf[tid][k + 2];
            float r = rs * (yip1 - 2.0f * yi + yim1);
            prev = (k == 0) ? r * w[0] : (r - prev) * w[k];
            dpS[tid][k] = prev;
            yim1 = yi; yi = yip1;
        }
        Ms[tid][63] = 0.0f;
        Ms[tid][0]  = 0.0f;
        float mnext = dpS[tid][61];
        Ms[tid][62] = mnext;
        #pragma unroll
        for (int k = 60; k >= 0; k--) {
            mnext = dpS[tid][k] - w[k] * Ms[tid][k + 2];
            Ms[tid][k + 1] = mnext;
        }
        spy[tid][63] = yf[tid][63];
    }
    __syncthreads();

    for (int e = tid; e < 6 * 63; e += IB_THR) {
        int ch = e / 63, i = e - ch * 63;
        float y0 = yf[ch][i], y1 = yf[ch][i + 1];
        float M0 = Ms[ch][i], M1 = Ms[ch][i + 1];
        float b = (y1 - y0) * 63.0f - (1.0f / 63.0f) * (2.0f * M0 + M1) * (1.0f / 6.0f);
        spy[ch][i] = y0;
        spb[ch][i] = b;
        spc[ch][i] = M0 * 0.5f;
        spd[ch][i] = (M1 - M0) * (63.0f / 6.0f);
    }
    __syncthreads();

    const double inv_nm1 = 1.0 / (double)(n - 1);
    int j0 = blockIdx.x * IB_SAMP + tid * 4;
    int zmin = 0x7fffffff;
    int zmax = 0;

    #pragma unroll
    for (int q = 0; q < 4; q++) {
        int j = j0 + q;
        if (j >= n) break;
        double td = (double)j * inv_nm1;
        float tf = (float)td;
        int i0 = (int)(td * 63.0);
        if (i0 > 62) i0 = 62;
        if (i0 < 0)  i0 = 0;
        while (i0 < 62 && tin_f(i0 + 1) <= tf) i0++;
        while (i0 > 0 && tin_f(i0) > tf) i0--;
        float dt = tf - tin_f(i0);

        float ch[6];
        #pragma unroll
        for (int cc = 0; cc < 6; cc++) {
            ch[cc] = spy[cc][i0] + spb[cc][i0] * dt
                   + spc[cc][i0] * dt * dt + spd[cc][i0] * dt * dt * dt;
        }

        float dl = ch[0];
        float zf = floorf(dl);
        int   z  = (int)zf;
        float alfa = dl - zf;
        float om = 1.0f - alfa;
        float b0 = ch[1], b1 = ch[2], b2 = ch[3], b3 = ch[4], b4 = ch[5];

        int zc = z; if (zc < 0) zc = 0; if (zc > ZCLAMP) zc = ZCLAMP;
        float x = (j < burst) ? exc[j] : 0.0f;

        float4 vA = make_float4(-om * b0,
                                -(alfa * b0 + om * b1),
                                -(alfa * b1 + om * b2),
                                -(alfa * b2 + om * b3));
        float4 vB = make_float4(-(alfa * b3 + om * b4),
                                -alfa * b4,
                                x,
                                __int_as_float(zc));
        g_vals4[(size_t)j * 2]     = vA;
        g_vals4[(size_t)j * 2 + 1] = vB;
        if (zc < zmin) zmin = zc;
        if (zc > zmax) zmax = zc;
    }

    // min/max over 8 consecutive lanes = one 32-sample block
    #pragma unroll
    for (int off = 4; off; off >>= 1) {
        int o = __shfl_xor_sync(0xffffffffu, zmin, off);
        if (o < zmin) zmin = o;
        int o2 = __shfl_xor_sync(0xffffffffu, zmax, off);
        if (o2 > zmax) zmax = o2;
    }
    if ((tid & 7) == 0) {
        int mi = j0 >> 5;
        if (mi < M32N) g_zmm[mi] = (zmin & 0xffff) | (zmax << 16);
    }
}

// ---------------- kernel 2: warp-ring pipelined IIR (no block barriers) ------
// Sub-chunk i = samples [32i, 32i+32), owned by warp i%16, lane = sample.
// RAW: wait acquire-flags [dlo_i, dhi_i] (from per-sub-chunk z min/max).
// WAR: before overwriting ring slots (written by own sub-chunk i-64), wait
//      flags [i-53, i-38]; with per-warp program order this covers all
//      readers (<= i-38) of the old data. Overwriters of OUR taps likewise
//      WAR-wait on us, so taps stay fresh. Deadlock-free for z >= 31.
__global__ void __launch_bounds__(512, 1)
iir_kernel(float* __restrict__ out, int n) {
    __shared__ float ring[RING];
    __shared__ int   flags[RING];   // one per sub-chunk (NS <= 2048)
    int tid = threadIdx.x;
    int w = tid >> 5, l = tid & 31;
    const float4* __restrict__ vals = g_vals4;

    for (int q = tid; q < RING; q += 512) { ring[q] = 0.0f; flags[q] = 0; }
    __syncthreads();     // only block barrier in the kernel

    const int NS = (n + 31) >> 5;

    float4 A0 = make_float4(0,0,0,0), B0 = A0, A1 = A0, B1 = A0, A2 = A0, B2 = A0;
    int Z0 = 0, Z1 = 0, Z2 = 0;

    #define LOADBUF(Ax, Bx, Zx, ii)                                             \
    {   int i__ = (ii);                                                         \
        if (i__ < NS) {                                                         \
            int t__ = (i__ << 5) + l;                                           \
            if (t__ < n) {                                                      \
                Ax = vals[(size_t)t__ * 2];                                     \
                Bx = vals[(size_t)t__ * 2 + 1];                                 \
            }                                                                   \
            Zx = g_zmm[i__];                                                    \
        } }

    LOADBUF(A0, B0, Z0, w);
    LOADBUF(A1, B1, Z1, w + 16);
    LOADBUF(A2, B2, Z2, w + 32);

    int i = w;

    #define ITER(Ax, Bx, Zx)                                                    \
    {                                                                           \
        int t    = (i << 5) + l;                                                \
        int z    = __float_as_int(Bx.w);                                        \
        int base = t - 1 - z;                                                   \
        int a0 = (base    ) & (RING - 1);                                       \
        int a1 = (base - 1) & (RING - 1);                                       \
        int a2 = (base - 2) & (RING - 1);                                       \
        int a3 = (base - 3) & (RING - 1);                                       \
        int a4 = (base - 4) & (RING - 1);                                       \
        int a5 = (base - 5) & (RING - 1);                                       \
        int zmin = Zx & 0xffff;                                                 \
        int zmax = (Zx >> 16) & 0xffff;                                         \
        int dhi = ((i << 5) + 30 - zmin) >> 5;                                  \
        int dlo = ((i << 5) - 6 - zmax) >> 5;                                   \
        if (dlo < 0) dlo = 0;                                                   \
        /* WAR wait: readers of our old ring slots must be done */              \
        if (i >= 38) {                                                          \
            int jj  = i - 53 + l;                                               \
            bool act = (l < 16) && (jj >= 0);                                   \
            for (;;) {                                                          \
                int f = act ? ld_acq(&flags[jj]) : 1;                           \
                if (__all_sync(0xffffffffu, f != 0)) break;                     \
            }                                                                   \
        }                                                                       \
        /* RAW wait: producer sub-chunks of our taps */                         \
        for (int j = dlo; j <= dhi; j++) {                                      \
            while (ld_acq(&flags[j]) == 0) { }                                  \
        }                                                                       \
        if (t < n) {                                                            \
            float r0 = ring[a0];                                                \
            float r1 = ring[a1];                                                \
            float r2 = ring[a2];                                                \
            float r3 = ring[a3];                                                \
            float r4 = ring[a4];                                                \
            float r5 = ring[a5];                                                \
            float p0 = Ax.x * r0 + Ax.z * r2 + Bx.x * r4;                       \
            float p1 = Ax.y * r1 + Ax.w * r3 + Bx.y * r5;                       \
            float acc = Bx.z - p0 - p1;                                         \
            ring[t & (RING - 1)] = acc;                                         \
            out[t] = acc;                                                       \
        }                                                                       \
        __syncwarp();                                                           \
        if (l == 0) st_rel(&flags[i], 1);                                       \
        LOADBUF(Ax, Bx, Zx, i + 48);     /* refill this buffer, depth-3 */      \
        i += 16;                                                                \
    }

    while (i < NS) {
        ITER(A0, B0, Z0);
        if (i >= NS) break;
        ITER(A1, B1, Z1);
        if (i >= NS) break;
        ITER(A2, B2, Z2);
    }
    #undef ITER
    #undef LOADBUF
}

// ---------------- launch ----------------
extern "C" void kernel_launch(void* const* d_in, const int* in_sizes, int n_in,
                              void* d_out, int out_size) {
    const float* delay = (const float*)d_in[0];
    const float* raw   = (const float*)d_in[1];
    const float* exc   = (const float*)d_in[2];
    int burst = in_sizes[2];
    int n = out_size;
    if (n > N_MAX) n = N_MAX;

    int iblocks = (n + IB_SAMP - 1) / IB_SAMP;
    interp_kernel<<<iblocks, IB_THR>>>(delay, raw, exc, burst, n);
    iir_kernel<<<1, 512>>>((float*)d_out, n);
}

// round 16
// speedup vs baseline: 1.0003x; 1.0003x over previous
#include <cuda_runtime.h>
#include <math.h>

#define N_MAX   65536
#define NF      64
#define LORD    5
#define RING    4096
#define NWARP   16
#define M32N    (N_MAX / 32)
#define ZCLAMP  801          // COEFF_VEC_SIZE(807) - (L_ORDER+1)
#define IB_SAMP 1024         // samples per interp block
#define IB_THR  256
#define W_INF   0.26794919243112270647f   // 2 - sqrt(3)

// ---------------- device scratch (no allocations allowed) ----------------
__device__ __align__(16) float4 g_vals4[N_MAX * 2];  // per sample: v0..v5, x, z_bits
__device__ int g_zmm[M32N];                          // per 32-sample: zmin | zmax<<16

__device__ __forceinline__ float tin_f(int i) {
    return (float)((double)i / 63.0);
}

__device__ __forceinline__ int ld_acq(const int* p) {
    int v;
    asm volatile("ld.acquire.cta.u32 %0, [%1];" : "=r"(v) : "l"(p) : "memory");
    return v;
}
__device__ __forceinline__ void st_rel(int* p, int v) {
    asm volatile("st.release.cta.u32 [%0], %1;" :: "l"(p), "r"(v) : "memory");
}

// ---------------- kernel 1: fused prep (per-block) + spline eval + taps ----------------
__global__ void __launch_bounds__(IB_THR)
interp_kernel(const float* __restrict__ delay, const float* __restrict__ raw,
              const float* __restrict__ exc, int burst, int n) {
    __shared__ float yf[6][NF];
    __shared__ float w[62];
    __shared__ float dpS[6][62];
    __shared__ float Ms[6][64];
    __shared__ float spy[6][64];
    __shared__ float spb[6][63];
    __shared__ float spc[6][63];
    __shared__ float spd[6][63];
    int tid = threadIdx.x;
    if (burst > n) burst = n;

    if (tid < NF) {
        float s[LORD]; float sum = 0.f;
        #pragma unroll
        for (int l = 0; l < LORD; l++) {
            s[l] = 1.0f / (1.0f + expf(-raw[tid * LORD + l]));
            sum += s[l];
        }
        #pragma unroll
        for (int l = 0; l < LORD; l++) yf[1 + l][tid] = s[l] / sum;
        yf[0][tid] = delay[tid];
    }
    if (tid == IB_THR - 1) {
        float wv = 0.25f; w[0] = wv;
        #pragma unroll
        for (int k = 1; k < 20; k++) { wv = 1.0f / (4.0f - wv); w[k] = wv; }
        #pragma unroll
        for (int k = 20; k < 62; k++) w[k] = W_INF;
    }
    __syncthreads();

    if (tid < 6) {
        const float rs = 6.0f * 63.0f * 63.0f;
        float yim1 = yf[tid][0];
        float yi   = yf[tid][1];
        float prev = 0.f;
        #pragma unroll
        for (int k = 0; k < 62; k++) {
            float yip1 = yf[tid][k + 2];
            float r = rs * (yip1 - 2.0f * yi + yim1);
            prev = (k == 0) ? r * w[0] : (r - prev) * w[k];
            dpS[tid][k] = prev;
            yim1 = yi; yi = yip1;
        }
        Ms[tid][63] = 0.0f;
        Ms[tid][0]  = 0.0f;
        float mnext = dpS[tid][61];
        Ms[tid][62] = mnext;
        #pragma unroll
        for (int k = 60; k >= 0; k--) {
            mnext = dpS[tid][k] - w[k] * Ms[tid][k + 2];
            Ms[tid][k + 1] = mnext;
        }
        spy[tid][63] = yf[tid][63];
    }
    __syncthreads();

    for (int e = tid; e < 6 * 63; e += IB_THR) {
        int ch = e / 63, i = e - ch * 63;
        float y0 = yf[ch][i], y1 = yf[ch][i + 1];
        float M0 = Ms[ch][i], M1 = Ms[ch][i + 1];
        float b = (y1 - y0) * 63.0f - (1.0f / 63.0f) * (2.0f * M0 + M1) * (1.0f / 6.0f);
        spy[ch][i] = y0;
        spb[ch][i] = b;
        spc[ch][i] = M0 * 0.5f;
        spd[ch][i] = (M1 - M0) * (63.0f / 6.0f);
    }
    __syncthreads();

    const double inv_nm1 = 1.0 / (double)(n - 1);
    int j0 = blockIdx.x * IB_SAMP + tid * 4;
    int zmin = 0x7fffffff;
    int zmax = 0;

    #pragma unroll
    for (int q = 0; q < 4; q++) {
        int j = j0 + q;
        if (j >= n) break;
        double td = (double)j * inv_nm1;
        float tf = (float)td;
        int i0 = (int)(td * 63.0);
        if (i0 > 62) i0 = 62;
        if (i0 < 0)  i0 = 0;
        while (i0 < 62 && tin_f(i0 + 1) <= tf) i0++;
        while (i0 > 0 && tin_f(i0) > tf) i0--;
        float dt = tf - tin_f(i0);

        float ch[6];
        #pragma unroll
        for (int cc = 0; cc < 6; cc++) {
            ch[cc] = spy[cc][i0] + spb[cc][i0] * dt
                   + spc[cc][i0] * dt * dt + spd[cc][i0] * dt * dt * dt;
        }

        float dl = ch[0];
        float zf = floorf(dl);
        int   z  = (int)zf;
        float alfa = dl - zf;
        float om = 1.0f - alfa;
        float b0 = ch[1], b1 = ch[2], b2 = ch[3], b3 = ch[4], b4 = ch[5];

        int zc = z; if (zc < 0) zc = 0; if (zc > ZCLAMP) zc = ZCLAMP;
        float x = (j < burst) ? exc[j] : 0.0f;

        float4 vA = make_float4(-om * b0,
                                -(alfa * b0 + om * b1),
                                -(alfa * b1 + om * b2),
                                -(alfa * b2 + om * b3));
        float4 vB = make_float4(-(alfa * b3 + om * b4),
                                -alfa * b4,
                                x,
                                __int_as_float(zc));
        g_vals4[(size_t)j * 2]     = vA;
        g_vals4[(size_t)j * 2 + 1] = vB;
        if (zc < zmin) zmin = zc;
        if (zc > zmax) zmax = zc;
    }

    #pragma unroll
    for (int off = 4; off; off >>= 1) {
        int o = __shfl_xor_sync(0xffffffffu, zmin, off);
        if (o < zmin) zmin = o;
        int o2 = __shfl_xor_sync(0xffffffffu, zmax, off);
        if (o2 > zmax) zmax = o2;
    }
    if ((tid & 7) == 0) {
        int mi = j0 >> 5;
        if (mi < M32N) g_zmm[mi] = (zmin & 0xffff) | (zmax << 16);
    }
}

// ---------------- kernel 2: warp-ring pipelined IIR (no block barriers) ------
// Sub-chunk i = samples [32i, 32i+32), owned by warp i%16, lane = sample.
// RING=4096: sub-chunk i overwrites slots last written by sub-chunk i-128;
// readers of that old data have index <= i-102, so the WAR wait
// (flags [i-117, i-102]) is satisfied ~always on first poll. RAW wait covers
// tap producers via per-sub-chunk z min/max. out[] STG is issued AFTER the
// flag release so the global-store drain is off the dependency chain.
__global__ void __launch_bounds__(512, 1)
iir_kernel(float* __restrict__ out, int n) {
    __shared__ float ring[RING];
    __shared__ int   flags[2048];   // one per sub-chunk (NS <= 2048)
    int tid = threadIdx.x;
    int w = tid >> 5, l = tid & 31;
    const float4* __restrict__ vals = g_vals4;

    for (int q = tid; q < RING; q += 512) ring[q] = 0.0f;
    for (int q = tid; q < 2048; q += 512) flags[q] = 0;
    __syncthreads();     // only block barrier in the kernel

    const int NS = (n + 31) >> 5;

    float4 A0 = make_float4(0,0,0,0), B0 = A0, A1 = A0, B1 = A0, A2 = A0, B2 = A0;
    int Z0 = 0, Z1 = 0, Z2 = 0;

    #define LOADBUF(Ax, Bx, Zx, ii)                                             \
    {   int i__ = (ii);                                                         \
        if (i__ < NS) {                                                         \
            int t__ = (i__ << 5) + l;                                           \
            if (t__ < n) {                                                      \
                Ax = vals[(size_t)t__ * 2];                                     \
                Bx = vals[(size_t)t__ * 2 + 1];                                 \
            }                                                                   \
            Zx = g_zmm[i__];                                                    \
        } }

    LOADBUF(A0, B0, Z0, w);
    LOADBUF(A1, B1, Z1, w + 16);
    LOADBUF(A2, B2, Z2, w + 32);

    int i = w;

    #define ITER(Ax, Bx, Zx)                                                    \
    {                                                                           \
        int t    = (i << 5) + l;                                                \
        int z    = __float_as_int(Bx.w);                                        \
        int base = t - 1 - z;                                                   \
        int a0 = (base    ) & (RING - 1);                                       \
        int a1 = (base - 1) & (RING - 1);                                       \
        int a2 = (base - 2) & (RING - 1);                                       \
        int a3 = (base - 3) & (RING - 1);                                       \
        int a4 = (base - 4) & (RING - 1);                                       \
        int a5 = (base - 5) & (RING - 1);                                       \
        int zmin = Zx & 0xffff;                                                 \
        int zmax = (Zx >> 16) & 0xffff;                                         \
        int dhi = ((i << 5) + 30 - zmin) >> 5;                                  \
        int dlo = ((i << 5) - 6 - zmax) >> 5;                                   \
        if (dlo < 0) dlo = 0;                                                   \
        /* WAR wait: readers (<= i-102) of our old ring slots must be done */   \
        if (i >= 102) {                                                         \
            int jj  = i - 117 + l;                                              \
            bool act = (l < 16) && (jj >= 0);                                   \
            for (;;) {                                                          \
                int f = act ? ld_acq(&flags[jj]) : 1;                           \
                if (__all_sync(0xffffffffu, f != 0)) break;                     \
            }                                                                   \
        }                                                                       \
        /* RAW wait: producer sub-chunks of our taps */                         \
        for (int j = dlo; j <= dhi; j++) {                                      \
            while (ld_acq(&flags[j]) == 0) { }                                  \
        }                                                                       \
        float acc = 0.f;                                                        \
        if (t < n) {                                                            \
            float r0 = ring[a0];                                                \
            float r1 = ring[a1];                                                \
            float r2 = ring[a2];                                                \
            float r3 = ring[a3];                                                \
            float r4 = ring[a4];                                                \
            float r5 = ring[a5];                                                \
            float p0 = Ax.x * r0 + Ax.z * r2 + Bx.x * r4;                       \
            float p1 = Ax.y * r1 + Ax.w * r3 + Bx.y * r5;                       \
            acc = Bx.z - p0 - p1;                                               \
            ring[t & (RING - 1)] = acc;                                         \
        }                                                                       \
        __syncwarp();                                                           \
        if (l == 0) st_rel(&flags[i], 1);   /* chain hop ends HERE */           \
        if (t < n) out[t] = acc;            /* global store off-chain */        \
        LOADBUF(Ax, Bx, Zx, i + 48);        /* refill this buffer, depth-3 */   \
        i += 16;                                                                \
    }

    while (i < NS) {
        ITER(A0, B0, Z0);
        if (i >= NS) break;
        ITER(A1, B1, Z1);
        if (i >= NS) break;
        ITER(A2, B2, Z2);
    }
    #undef ITER
    #undef LOADBUF
}

// ---------------- launch ----------------
extern "C" void kernel_launch(void* const* d_in, const int* in_sizes, int n_in,
                              void* d_out, int out_size) {
    const float* delay = (const float*)d_in[0];
    const float* raw   = (const float*)d_in[1];
    const float* exc   = (const float*)d_in[2];
    int burst = in_sizes[2];
    int n = out_size;
    if (n > N_MAX) n = N_MAX;

    int iblocks = (n + IB_SAMP - 1) / IB_SAMP;
    interp_kernel<<<iblocks, IB_THR>>>(delay, raw, exc, burst, n);
    iir_kernel<<<1, 512>>>((float*)d_out, n);
}